// round 14
// baseline (speedup 1.0000x reference)
#include <cuda_runtime.h>

#define Hn 9
#define Wn 10
#define Dn 5
#define KD 3            // Dn/2 + 1
#define DIMC 1000
#define NSP (Hn*Wn*Dn)  // 450
#define CT 20           // channels per block tile (1000/20 = 50 tiles)
#define NTHREADS 256
#define SC (1.0f/450.0f)

// ---- compile-time twiddle literals (FFMA immediates) ----
#define C51  0.30901699437494745f
#define C52 (-0.8090169943749475f)
#define S51  0.9510565162951535f
#define S52  0.5877852522924731f
#define S3   0.8660254037844386f
#define C91  0.766044443118978f
#define S91  0.6427876096865393f
#define C92  0.17364817766693041f
#define S92  0.984807753012208f
#define C94 (-0.9396926207859084f)
#define S94  0.3420201433256687f
#define C101 0.8090169943749475f
#define S101 0.5877852522924731f
#define C102 0.30901699437494745f
#define S102 0.9510565162951535f
// output-stage constants with 1/450 and the rfft doubling folded in
#define TWOSC (2.0f*SC)
#define C51T (2.0f*SC*C51)
#define C52T (2.0f*SC*C52)
#define S51T (2.0f*SC*S51)
#define S52T (2.0f*SC*S52)

__device__ __forceinline__ float2 cadd(float2 a, float2 b){ return make_float2(a.x+b.x, a.y+b.y); }
__device__ __forceinline__ float2 csub(float2 a, float2 b){ return make_float2(a.x-b.x, a.y-b.y); }
__device__ __forceinline__ float2 cmul(float2 a, float c, float s){
    return make_float2(a.x*c - a.y*s, a.y*c + a.x*s);
}
__device__ __forceinline__ float2 wmul(float2 a, float2 g){
    return make_float2(a.x*g.x - a.y*g.y, a.x*g.y + a.y*g.x);
}

template<int SGN>
__device__ __forceinline__ void dft3(float2 a0, float2 a1, float2 a2,
                                     float2& X0, float2& X1, float2& X2){
    float2 t = cadd(a1,a2), d = csub(a1,a2);
    X0 = cadd(a0,t);
    float mr = fmaf(-0.5f, t.x, a0.x);
    float mi = fmaf(-0.5f, t.y, a0.y);
    const float s = (SGN > 0) ? S3 : -S3;
    X1 = make_float2(fmaf( s, d.y, mr), fmaf(-s, d.x, mi));
    X2 = make_float2(fmaf(-s, d.y, mr), fmaf( s, d.x, mi));
}

template<int SGN>
__device__ __forceinline__ void dft5(float2 a0, float2 a1, float2 a2, float2 a3, float2 a4,
                                     float2& X0, float2& X1, float2& X2, float2& X3, float2& X4){
    float2 t1 = cadd(a1,a4), t2 = cadd(a2,a3), t3 = csub(a1,a4), t4 = csub(a2,a3);
    X0 = make_float2(a0.x + t1.x + t2.x, a0.y + t1.y + t2.y);
    float u1r = a0.x + C51*t1.x + C52*t2.x;
    float u1i = a0.y + C51*t1.y + C52*t2.y;
    float v1r = S51*t3.x + S52*t4.x;
    float v1i = S51*t3.y + S52*t4.y;
    float u2r = a0.x + C52*t1.x + C51*t2.x;
    float u2i = a0.y + C52*t1.y + C51*t2.y;
    float v2r = S52*t3.x - S51*t4.x;
    float v2i = S52*t3.y - S51*t4.y;
    if (SGN > 0){
        X1 = make_float2(u1r + v1i, u1i - v1r);
        X4 = make_float2(u1r - v1i, u1i + v1r);
        X2 = make_float2(u2r + v2i, u2i - v2r);
        X3 = make_float2(u2r - v2i, u2i + v2r);
    } else {
        X1 = make_float2(u1r - v1i, u1i + v1r);
        X4 = make_float2(u1r + v1i, u1i - v1r);
        X2 = make_float2(u2r - v2i, u2i + v2r);
        X3 = make_float2(u2r + v2i, u2i - v2r);
    }
}

// real-input 5-pt DFT (forward): 5 reals -> F0 (real), F1, F2 (F3=conj(F2), F4=conj(F1))
__device__ __forceinline__ void rdft5(float a0, float a1, float a2, float a3, float a4,
                                      float& F0, float2& F1, float2& F2){
    float t1=a1+a4, t2=a2+a3, t3=a1-a4, t4=a2-a3;
    F0 = a0 + t1 + t2;
    F1 = make_float2(a0 + C51*t1 + C52*t2, -(S51*t3 + S52*t4));
    F2 = make_float2(a0 + C52*t1 + C51*t2, -(S52*t3 - S51*t4));
}

// 10-pt FFT on ten named scalars, radix 2x5 DIT
template<int SGN>
__device__ __forceinline__ void fft10s(float2&x0, float2&x1, float2&x2, float2&x3, float2&x4,
                                       float2&x5, float2&x6, float2&x7, float2&x8, float2&x9){
    float2 E0,E1,E2,E3,E4, O0,O1,O2,O3,O4;
    dft5<SGN>(x0,x2,x4,x6,x8, E0,E1,E2,E3,E4);
    dft5<SGN>(x1,x3,x5,x7,x9, O0,O1,O2,O3,O4);
    const float sg = (SGN > 0) ? -1.0f : 1.0f;
    float2 T1 = cmul(O1,  C101, sg*S101);
    float2 T2 = cmul(O2,  C102, sg*S102);
    float2 T3 = cmul(O3, -C102, sg*S102);
    float2 T4 = cmul(O4, -C101, sg*S101);
    x0=cadd(E0,O0); x5=csub(E0,O0);
    x1=cadd(E1,T1); x6=csub(E1,T1);
    x2=cadd(E2,T2); x7=csub(E2,T2);
    x3=cadd(E3,T3); x8=csub(E3,T3);
    x4=cadd(E4,T4); x9=csub(E4,T4);
}

// inverse 10-pt FFT, REAL PARTS ONLY of the outputs (inputs complex, general)
__device__ __forceinline__ void ifft10_re(
    float2 p0, float2 p1, float2 p2, float2 p3, float2 p4,
    float2 p5, float2 p6, float2 p7, float2 p8, float2 p9,
    float&s0,float&s1,float&s2,float&s3,float&s4,
    float&s5,float&s6,float&s7,float&s8,float&s9){
    float2 E0,E1,E2,E3,E4, O0,O1,O2,O3,O4;
    dft5<-1>(p0,p2,p4,p6,p8, E0,E1,E2,E3,E4);
    dft5<-1>(p1,p3,p5,p7,p9, O0,O1,O2,O3,O4);
    // Re(w_j * O_j), inverse twiddles w_j = e^{+2pi i j/10}
    float Tr1 =  C101*O1.x - S101*O1.y;
    float Tr2 =  C102*O2.x - S102*O2.y;
    float Tr3 = -C102*O3.x - S102*O3.y;
    float Tr4 = -C101*O4.x - S101*O4.y;
    s0 = E0.x + O0.x;  s5 = E0.x - O0.x;
    s1 = E1.x + Tr1;   s6 = E1.x - Tr1;
    s2 = E2.x + Tr2;   s7 = E2.x - Tr2;
    s3 = E3.x + Tr3;   s8 = E3.x - Tr3;
    s4 = E4.x + Tr4;   s9 = E4.x - Tr4;
}

// ---- Phase A pass 1: load d-column at w, emit k0 (real) + k1 ----
#define P1W(w) do { \
    float v0 = px[((w)*Dn+0)*DIMC], v1 = px[((w)*Dn+1)*DIMC], \
          v2 = px[((w)*Dn+2)*DIMC], v3 = px[((w)*Dn+3)*DIMC], \
          v4 = px[((w)*Dn+4)*DIMC]; \
    float t1 = v1+v4, t2 = v2+v3, t3 = v1-v4, t4 = v2-v3; \
    a##w = v0 + t1 + t2; \
    q##w = make_float2(v0 + C51*t1 + C52*t2, -(S51*t3 + S52*t4)); \
} while(0)

// ---- Phase A pass 2: reload d-column at w, emit k2 ----
#define P2W(w) do { \
    float v0 = px[((w)*Dn+0)*DIMC], v1 = px[((w)*Dn+1)*DIMC], \
          v2 = px[((w)*Dn+2)*DIMC], v3 = px[((w)*Dn+3)*DIMC], \
          v4 = px[((w)*Dn+4)*DIMC]; \
    float t1 = v1+v4, t2 = v2+v3, t3 = v1-v4, t4 = v2-v3; \
    q##w = make_float2(v0 + C52*t1 + C51*t2, -(S52*t3 - S51*t4)); \
} while(0)

#define FFT10Q(SGN) fft10s<SGN>(q0,q1,q2,q3,q4,q5,q6,q7,q8,q9)

#define STOREQ(K) do { \
    z[zb + (0*KD+(K))*CT] = q0; z[zb + (1*KD+(K))*CT] = q1; \
    z[zb + (2*KD+(K))*CT] = q2; z[zb + (3*KD+(K))*CT] = q3; \
    z[zb + (4*KD+(K))*CT] = q4; z[zb + (5*KD+(K))*CT] = q5; \
    z[zb + (6*KD+(K))*CT] = q6; z[zb + (7*KD+(K))*CT] = q7; \
    z[zb + (8*KD+(K))*CT] = q8; z[zb + (9*KD+(K))*CT] = q9; \
} while(0)

#define LOADQ(K) do { \
    q0 = z[zb + (0*KD+(K))*CT]; q1 = z[zb + (1*KD+(K))*CT]; \
    q2 = z[zb + (2*KD+(K))*CT]; q3 = z[zb + (3*KD+(K))*CT]; \
    q4 = z[zb + (4*KD+(K))*CT]; q5 = z[zb + (5*KD+(K))*CT]; \
    q6 = z[zb + (6*KD+(K))*CT]; q7 = z[zb + (7*KD+(K))*CT]; \
    q8 = z[zb + (8*KD+(K))*CT]; q9 = z[zb + (9*KD+(K))*CT]; \
} while(0)

#define LOADU(K) do { \
    u0 = z[zb + (0*KD+(K))*CT]; u1 = z[zb + (1*KD+(K))*CT]; \
    u2 = z[zb + (2*KD+(K))*CT]; u3 = z[zb + (3*KD+(K))*CT]; \
    u4 = z[zb + (4*KD+(K))*CT]; u5 = z[zb + (5*KD+(K))*CT]; \
    u6 = z[zb + (6*KD+(K))*CT]; u7 = z[zb + (7*KD+(K))*CT]; \
    u8 = z[zb + (8*KD+(K))*CT]; u9 = z[zb + (9*KD+(K))*CT]; \
} while(0)

// irfft5 + store for one w: s##w real (k0), u##w (k1), q##w (k2)
#define OUTW(w) do { \
    float s0_ = SC * s##w; \
    float r1 = u##w.x, i1 = u##w.y, r2 = q##w.x, i2 = q##w.y; \
    float pA = s0_ + C51T*r1 + C52T*r2; \
    float qA = S51T*i1 + S52T*i2; \
    float pB = s0_ + C52T*r1 + C51T*r2; \
    float qB = S52T*i1 - S51T*i2; \
    po[((w)*Dn+0)*DIMC] = s0_ + TWOSC*(r1 + r2); \
    po[((w)*Dn+1)*DIMC] = pA - qA; \
    po[((w)*Dn+2)*DIMC] = pB - qB; \
    po[((w)*Dn+3)*DIMC] = pB + qB; \
    po[((w)*Dn+4)*DIMC] = pA + qA; \
} while(0)

// Shared layout: z[((h*Wn + w)*KD + k)*CT + c] as float2 — 43.2 KB STATIC.
__global__ void __launch_bounds__(NTHREADS)
gf_kernel(const float* __restrict__ x, const float2* __restrict__ cw2,
          float* __restrict__ out)
{
    __shared__ float2 z[Hn*Wn*KD*CT];

    const int b   = blockIdx.x;
    const int c0  = blockIdx.y * CT;
    const int tid = threadIdx.x;
    const long xbase = (long)b * NSP * DIMC + c0;

    // ---- Phase A: thread owns (h, c) pencil. Two passes over x to keep the
    //      live set under the 64-register allocation (pass2 reload = L2 hits).
    for (int it = tid; it < Hn*CT; it += NTHREADS) {
        int c = it % CT, h = it / CT;
        const float* px = x + xbase + (long)h * (Wn*Dn*DIMC) + c;
        int zb = (h*Wn*KD)*CT + c;
        // pass 1: k0 (real, 10 floats) + k1 (10 float2)
        float a0,a1,a2,a3,a4,a5,a6,a7,a8,a9;
        float2 q0,q1,q2,q3,q4,q5,q6,q7,q8,q9;
        P1W(0); P1W(1); P1W(2); P1W(3); P1W(4);
        P1W(5); P1W(6); P1W(7); P1W(8); P1W(9);
        FFT10Q(+1); STOREQ(1);
        // real-input fft10 on k0 plane (Hermitian output)
        {
            float E0r, O0r; float2 E1,E2,O1,O2;
            rdft5(a0,a2,a4,a6,a8, E0r,E1,E2);
            rdft5(a1,a3,a5,a7,a9, O0r,O1,O2);
            float2 T1 = cmul(O1, C101, -S101);
            float2 T2 = cmul(O2, C102, -S102);
            z[zb + (0*KD)*CT] = make_float2(E0r + O0r, 0.0f);
            z[zb + (5*KD)*CT] = make_float2(E0r - O0r, 0.0f);
            float2 X1 = cadd(E1,T1), X6 = csub(E1,T1);
            float2 X2 = cadd(E2,T2), X7 = csub(E2,T2);
            z[zb + (1*KD)*CT] = X1;
            z[zb + (6*KD)*CT] = X6;
            z[zb + (2*KD)*CT] = X2;
            z[zb + (7*KD)*CT] = X7;
            z[zb + (3*KD)*CT] = make_float2(X7.x, -X7.y);
            z[zb + (4*KD)*CT] = make_float2(X6.x, -X6.y);
            z[zb + (8*KD)*CT] = make_float2(X2.x, -X2.y);
            z[zb + (9*KD)*CT] = make_float2(X1.x, -X1.y);
        }
        // pass 2: reload x, k2 plane (compiler barrier stops CSE with pass 1)
        asm volatile("" ::: "memory");
        P2W(0); P2W(1); P2W(2); P2W(3); P2W(4);
        P2W(5); P2W(6); P2W(7); P2W(8); P2W(9);
        FFT10Q(+1); STOREQ(2);
    }
    __syncthreads();

    // ---- Phase B: fwd 9-pt (3x3) -> weight -> inv 9-pt, in registers
    {
        const int HS = Wn*KD*CT;
        const int WS = Wn*KD*DIMC;
        for (int it = tid; it < Wn*KD*CT; it += NTHREADS) {
            int c  = it % CT;
            int wk = it / CT;
            int w = wk / KD, k = wk % KD;
            int base = (w*KD + k)*CT + c;
            const float2* cwp = cw2 + (long)((w*KD) + k)*DIMC + c0 + c;
            float2 a0=z[base+0*HS], a1=z[base+1*HS], a2=z[base+2*HS],
                   a3=z[base+3*HS], a4=z[base+4*HS], a5=z[base+5*HS],
                   a6=z[base+6*HS], a7=z[base+7*HS], a8=z[base+8*HS];
            float2 A00,A10,A20, A01,A11,A21, A02,A12,A22;
            dft3<+1>(a0,a3,a6, A00,A10,A20);
            dft3<+1>(a1,a4,a7, A01,A11,A21);
            dft3<+1>(a2,a5,a8, A02,A12,A22);
            A11 = cmul(A11, C91, -S91);
            A12 = cmul(A12, C92, -S92);
            A21 = cmul(A21, C92, -S92);
            A22 = cmul(A22, C94, -S94);
            float2 X0,X3,X6, X1,X4,X7, X2,X5,X8;
            dft3<+1>(A00,A01,A02, X0,X3,X6);
            dft3<+1>(A10,A11,A12, X1,X4,X7);
            dft3<+1>(A20,A21,A22, X2,X5,X8);
            X0 = wmul(X0, cwp[0*WS]); X1 = wmul(X1, cwp[1*WS]); X2 = wmul(X2, cwp[2*WS]);
            X3 = wmul(X3, cwp[3*WS]); X4 = wmul(X4, cwp[4*WS]); X5 = wmul(X5, cwp[5*WS]);
            X6 = wmul(X6, cwp[6*WS]); X7 = wmul(X7, cwp[7*WS]); X8 = wmul(X8, cwp[8*WS]);
            float2 P00,P10,P20, P01,P11,P21, P02,P12,P22;
            dft3<-1>(X0,X3,X6, P00,P10,P20);
            dft3<-1>(X1,X4,X7, P01,P11,P21);
            dft3<-1>(X2,X5,X8, P02,P12,P22);
            P11 = cmul(P11, C91, S91);
            P12 = cmul(P12, C92, S92);
            P21 = cmul(P21, C92, S92);
            P22 = cmul(P22, C94, S94);
            float2 y0,y3,y6, y1,y4,y7, y2,y5,y8;
            dft3<-1>(P00,P01,P02, y0,y3,y6);
            dft3<-1>(P10,P11,P12, y1,y4,y7);
            dft3<-1>(P20,P21,P22, y2,y5,y8);
            z[base+0*HS]=y0; z[base+1*HS]=y1; z[base+2*HS]=y2;
            z[base+3*HS]=y3; z[base+4*HS]=y4; z[base+5*HS]=y5;
            z[base+6*HS]=y6; z[base+7*HS]=y7; z[base+8*HS]=y8;
        }
    }
    __syncthreads();

    // ---- Phase C: thread owns (h, c) pencil. k0 first with Re-only ifft10
    //      (10 floats), then k1 and k2 full; combine via irfft5 and store.
    for (int it = tid; it < Hn*CT; it += NTHREADS) {
        int c = it % CT, h = it / CT;
        int zb = (h*Wn*KD)*CT + c;
        float s0,s1,s2,s3,s4,s5,s6,s7,s8,s9;
        float2 u0,u1,u2,u3,u4,u5,u6,u7,u8,u9;
        float2 q0,q1,q2,q3,q4,q5,q6,q7,q8,q9;
        LOADQ(0);
        ifft10_re(q0,q1,q2,q3,q4,q5,q6,q7,q8,q9,
                  s0,s1,s2,s3,s4,s5,s6,s7,s8,s9);
        LOADU(1);
        fft10s<-1>(u0,u1,u2,u3,u4,u5,u6,u7,u8,u9);
        LOADQ(2);
        FFT10Q(-1);
        float* po = out + xbase + (long)h * (Wn*Dn*DIMC) + c;
        OUTW(0); OUTW(1); OUTW(2); OUTW(3); OUTW(4);
        OUTW(5); OUTW(6); OUTW(7); OUTW(8); OUTW(9);
    }
}

extern "C" void kernel_launch(void* const* d_in, const int* in_sizes, int n_in,
                              void* d_out, int out_size) {
    const float*  x   = (const float*)d_in[0];    // (B, 450, 1000) f32
    const float2* cw2 = (const float2*)d_in[1];   // (9, 10, 3, 1000, 2) f32
    float* out = (float*)d_out;                   // (B, 450, 1000) f32
    const int B = in_sizes[0] / (NSP * DIMC);
    dim3 grid(B, DIMC / CT);
    gf_kernel<<<grid, NTHREADS>>>(x, cw2, out);
}

// round 15
// speedup vs baseline: 1.2483x; 1.2483x over previous
#include <cuda_runtime.h>

#define Hn 9
#define Wn 10
#define Dn 5
#define KD 3            // Dn/2 + 1
#define DIMC 1000
#define NSP (Hn*Wn*Dn)  // 450
#define CT 20           // channels per block tile (1000/20 = 50 tiles)
#define NTHREADS 256
#define SC (1.0f/450.0f)

// ---- compile-time twiddle literals (FFMA immediates) ----
#define C51  0.30901699437494745f
#define C52 (-0.8090169943749475f)
#define S51  0.9510565162951535f
#define S52  0.5877852522924731f
#define S3   0.8660254037844386f
#define C91  0.766044443118978f
#define S91  0.6427876096865393f
#define C92  0.17364817766693041f
#define S92  0.984807753012208f
#define C94 (-0.9396926207859084f)
#define S94  0.3420201433256687f
#define C101 0.8090169943749475f
#define S101 0.5877852522924731f
#define C102 0.30901699437494745f
#define S102 0.9510565162951535f
// output-stage constants with 1/450 and the rfft doubling folded in
#define TWOSC (2.0f*SC)
#define C51T (2.0f*SC*C51)
#define C52T (2.0f*SC*C52)
#define S51T (2.0f*SC*S51)
#define S52T (2.0f*SC*S52)

__device__ __forceinline__ float2 cadd(float2 a, float2 b){ return make_float2(a.x+b.x, a.y+b.y); }
__device__ __forceinline__ float2 csub(float2 a, float2 b){ return make_float2(a.x-b.x, a.y-b.y); }
__device__ __forceinline__ float2 cmul(float2 a, float c, float s){
    return make_float2(a.x*c - a.y*s, a.y*c + a.x*s);
}
__device__ __forceinline__ float2 wmul(float2 a, float2 g){
    return make_float2(a.x*g.x - a.y*g.y, a.x*g.y + a.y*g.x);
}

template<int SGN>
__device__ __forceinline__ void dft3(float2 a0, float2 a1, float2 a2,
                                     float2& X0, float2& X1, float2& X2){
    float2 t = cadd(a1,a2), d = csub(a1,a2);
    X0 = cadd(a0,t);
    float mr = fmaf(-0.5f, t.x, a0.x);
    float mi = fmaf(-0.5f, t.y, a0.y);
    const float s = (SGN > 0) ? S3 : -S3;
    X1 = make_float2(fmaf( s, d.y, mr), fmaf(-s, d.x, mi));
    X2 = make_float2(fmaf(-s, d.y, mr), fmaf( s, d.x, mi));
}

template<int SGN>
__device__ __forceinline__ void dft5(float2 a0, float2 a1, float2 a2, float2 a3, float2 a4,
                                     float2& X0, float2& X1, float2& X2, float2& X3, float2& X4){
    float2 t1 = cadd(a1,a4), t2 = cadd(a2,a3), t3 = csub(a1,a4), t4 = csub(a2,a3);
    X0 = make_float2(a0.x + t1.x + t2.x, a0.y + t1.y + t2.y);
    float u1r = a0.x + C51*t1.x + C52*t2.x;
    float u1i = a0.y + C51*t1.y + C52*t2.y;
    float v1r = S51*t3.x + S52*t4.x;
    float v1i = S51*t3.y + S52*t4.y;
    float u2r = a0.x + C52*t1.x + C51*t2.x;
    float u2i = a0.y + C52*t1.y + C51*t2.y;
    float v2r = S52*t3.x - S51*t4.x;
    float v2i = S52*t3.y - S51*t4.y;
    if (SGN > 0){
        X1 = make_float2(u1r + v1i, u1i - v1r);
        X4 = make_float2(u1r - v1i, u1i + v1r);
        X2 = make_float2(u2r + v2i, u2i - v2r);
        X3 = make_float2(u2r - v2i, u2i + v2r);
    } else {
        X1 = make_float2(u1r - v1i, u1i + v1r);
        X4 = make_float2(u1r + v1i, u1i - v1r);
        X2 = make_float2(u2r - v2i, u2i + v2r);
        X3 = make_float2(u2r + v2i, u2i - v2r);
    }
}

// real-input 5-pt DFT (forward): 5 reals -> F0 (real), F1, F2 (F3=conj(F2), F4=conj(F1))
__device__ __forceinline__ void rdft5(float a0, float a1, float a2, float a3, float a4,
                                      float& F0, float2& F1, float2& F2){
    float t1=a1+a4, t2=a2+a3, t3=a1-a4, t4=a2-a3;
    F0 = a0 + t1 + t2;
    F1 = make_float2(a0 + C51*t1 + C52*t2, -(S51*t3 + S52*t4));
    F2 = make_float2(a0 + C52*t1 + C51*t2, -(S52*t3 - S51*t4));
}

// 10-pt FFT on ten named scalars, radix 2x5 DIT
template<int SGN>
__device__ __forceinline__ void fft10s(float2&x0, float2&x1, float2&x2, float2&x3, float2&x4,
                                       float2&x5, float2&x6, float2&x7, float2&x8, float2&x9){
    float2 E0,E1,E2,E3,E4, O0,O1,O2,O3,O4;
    dft5<SGN>(x0,x2,x4,x6,x8, E0,E1,E2,E3,E4);
    dft5<SGN>(x1,x3,x5,x7,x9, O0,O1,O2,O3,O4);
    const float sg = (SGN > 0) ? -1.0f : 1.0f;
    float2 T1 = cmul(O1,  C101, sg*S101);
    float2 T2 = cmul(O2,  C102, sg*S102);
    float2 T3 = cmul(O3, -C102, sg*S102);
    float2 T4 = cmul(O4, -C101, sg*S101);
    x0=cadd(E0,O0); x5=csub(E0,O0);
    x1=cadd(E1,T1); x6=csub(E1,T1);
    x2=cadd(E2,T2); x7=csub(E2,T2);
    x3=cadd(E3,T3); x8=csub(E3,T3);
    x4=cadd(E4,T4); x9=csub(E4,T4);
}

// inverse 10-pt FFT, REAL PARTS ONLY of the outputs (inputs complex, general)
__device__ __forceinline__ void ifft10_re(
    float2 p0, float2 p1, float2 p2, float2 p3, float2 p4,
    float2 p5, float2 p6, float2 p7, float2 p8, float2 p9,
    float&s0,float&s1,float&s2,float&s3,float&s4,
    float&s5,float&s6,float&s7,float&s8,float&s9){
    float2 E0,E1,E2,E3,E4, O0,O1,O2,O3,O4;
    dft5<-1>(p0,p2,p4,p6,p8, E0,E1,E2,E3,E4);
    dft5<-1>(p1,p3,p5,p7,p9, O0,O1,O2,O3,O4);
    // Re(w_j * O_j), inverse twiddles w_j = e^{+2pi i j/10}
    float Tr1 =  C101*O1.x - S101*O1.y;
    float Tr2 =  C102*O2.x - S102*O2.y;
    float Tr3 = -C102*O3.x - S102*O3.y;
    float Tr4 = -C101*O4.x - S101*O4.y;
    s0 = E0.x + O0.x;  s5 = E0.x - O0.x;
    s1 = E1.x + Tr1;   s6 = E1.x - Tr1;
    s2 = E2.x + Tr2;   s7 = E2.x - Tr2;
    s3 = E3.x + Tr3;   s8 = E3.x - Tr3;
    s4 = E4.x + Tr4;   s9 = E4.x - Tr4;
}

// ---- Phase A: load d-column at w, emit all three planes:
//      a (k0, real), q (k1), g (k2). Single pass over x.
#define AW(w) do { \
    float v0 = px[((w)*Dn+0)*DIMC], v1 = px[((w)*Dn+1)*DIMC], \
          v2 = px[((w)*Dn+2)*DIMC], v3 = px[((w)*Dn+3)*DIMC], \
          v4 = px[((w)*Dn+4)*DIMC]; \
    float t1 = v1+v4, t2 = v2+v3, t3 = v1-v4, t4 = v2-v3; \
    a##w = v0 + t1 + t2; \
    q##w = make_float2(v0 + C51*t1 + C52*t2, -(S51*t3 + S52*t4)); \
    g##w = make_float2(v0 + C52*t1 + C51*t2, -(S52*t3 - S51*t4)); \
} while(0)

#define STOREQ(K) do { \
    z[zb + (0*KD+(K))*CT] = q0; z[zb + (1*KD+(K))*CT] = q1; \
    z[zb + (2*KD+(K))*CT] = q2; z[zb + (3*KD+(K))*CT] = q3; \
    z[zb + (4*KD+(K))*CT] = q4; z[zb + (5*KD+(K))*CT] = q5; \
    z[zb + (6*KD+(K))*CT] = q6; z[zb + (7*KD+(K))*CT] = q7; \
    z[zb + (8*KD+(K))*CT] = q8; z[zb + (9*KD+(K))*CT] = q9; \
} while(0)

#define STOREG(K) do { \
    z[zb + (0*KD+(K))*CT] = g0; z[zb + (1*KD+(K))*CT] = g1; \
    z[zb + (2*KD+(K))*CT] = g2; z[zb + (3*KD+(K))*CT] = g3; \
    z[zb + (4*KD+(K))*CT] = g4; z[zb + (5*KD+(K))*CT] = g5; \
    z[zb + (6*KD+(K))*CT] = g6; z[zb + (7*KD+(K))*CT] = g7; \
    z[zb + (8*KD+(K))*CT] = g8; z[zb + (9*KD+(K))*CT] = g9; \
} while(0)

#define LOADQ(K) do { \
    q0 = z[zb + (0*KD+(K))*CT]; q1 = z[zb + (1*KD+(K))*CT]; \
    q2 = z[zb + (2*KD+(K))*CT]; q3 = z[zb + (3*KD+(K))*CT]; \
    q4 = z[zb + (4*KD+(K))*CT]; q5 = z[zb + (5*KD+(K))*CT]; \
    q6 = z[zb + (6*KD+(K))*CT]; q7 = z[zb + (7*KD+(K))*CT]; \
    q8 = z[zb + (8*KD+(K))*CT]; q9 = z[zb + (9*KD+(K))*CT]; \
} while(0)

#define LOADU(K) do { \
    u0 = z[zb + (0*KD+(K))*CT]; u1 = z[zb + (1*KD+(K))*CT]; \
    u2 = z[zb + (2*KD+(K))*CT]; u3 = z[zb + (3*KD+(K))*CT]; \
    u4 = z[zb + (4*KD+(K))*CT]; u5 = z[zb + (5*KD+(K))*CT]; \
    u6 = z[zb + (6*KD+(K))*CT]; u7 = z[zb + (7*KD+(K))*CT]; \
    u8 = z[zb + (8*KD+(K))*CT]; u9 = z[zb + (9*KD+(K))*CT]; \
} while(0)

// irfft5 + store for one w: s##w real (k0), u##w (k1), q##w (k2)
#define OUTW(w) do { \
    float s0_ = SC * s##w; \
    float r1 = u##w.x, i1 = u##w.y, r2 = q##w.x, i2 = q##w.y; \
    float pA = s0_ + C51T*r1 + C52T*r2; \
    float qA = S51T*i1 + S52T*i2; \
    float pB = s0_ + C52T*r1 + C51T*r2; \
    float qB = S52T*i1 - S51T*i2; \
    po[((w)*Dn+0)*DIMC] = s0_ + TWOSC*(r1 + r2); \
    po[((w)*Dn+1)*DIMC] = pA - qA; \
    po[((w)*Dn+2)*DIMC] = pB - qB; \
    po[((w)*Dn+3)*DIMC] = pB + qB; \
    po[((w)*Dn+4)*DIMC] = pA + qA; \
} while(0)

// Shared layout: z[((h*Wn + w)*KD + k)*CT + c] as float2 — 43.2 KB STATIC.
__global__ void __launch_bounds__(NTHREADS)
gf_kernel(const float* __restrict__ x, const float2* __restrict__ cw2,
          float* __restrict__ out)
{
    __shared__ float2 z[Hn*Wn*KD*CT];

    const int b   = blockIdx.x;
    const int c0  = blockIdx.y * CT;
    const int tid = threadIdx.x;
    const long xbase = (long)b * NSP * DIMC + c0;

    // ---- Phase A: thread owns (h, c) pencil. ONE pass over x (50 LDGs),
    //      k0 plane kept real (rfft5 DC), k1/k2 complex. rfft10 on the real
    //      plane first (smallest temps -> lowest peak live set), then k1, k2.
    for (int it = tid; it < Hn*CT; it += NTHREADS) {
        int c = it % CT, h = it / CT;
        const float* px = x + xbase + (long)h * (Wn*Dn*DIMC) + c;
        int zb = (h*Wn*KD)*CT + c;
        float a0,a1,a2,a3,a4,a5,a6,a7,a8,a9;
        float2 q0,q1,q2,q3,q4,q5,q6,q7,q8,q9;
        float2 g0,g1,g2,g3,g4,g5,g6,g7,g8,g9;
        AW(0); AW(1); AW(2); AW(3); AW(4);
        AW(5); AW(6); AW(7); AW(8); AW(9);
        // real-input fft10 on k0 plane (Hermitian output), store k=0
        {
            float E0r, O0r; float2 E1,E2,O1,O2;
            rdft5(a0,a2,a4,a6,a8, E0r,E1,E2);
            rdft5(a1,a3,a5,a7,a9, O0r,O1,O2);
            float2 T1 = cmul(O1, C101, -S101);
            float2 T2 = cmul(O2, C102, -S102);
            z[zb + (0*KD)*CT] = make_float2(E0r + O0r, 0.0f);
            z[zb + (5*KD)*CT] = make_float2(E0r - O0r, 0.0f);
            float2 X1 = cadd(E1,T1), X6 = csub(E1,T1);
            float2 X2 = cadd(E2,T2), X7 = csub(E2,T2);
            z[zb + (1*KD)*CT] = X1;
            z[zb + (6*KD)*CT] = X6;
            z[zb + (2*KD)*CT] = X2;
            z[zb + (7*KD)*CT] = X7;
            z[zb + (3*KD)*CT] = make_float2(X7.x, -X7.y);
            z[zb + (4*KD)*CT] = make_float2(X6.x, -X6.y);
            z[zb + (8*KD)*CT] = make_float2(X2.x, -X2.y);
            z[zb + (9*KD)*CT] = make_float2(X1.x, -X1.y);
        }
        fft10s<+1>(q0,q1,q2,q3,q4,q5,q6,q7,q8,q9); STOREQ(1);
        fft10s<+1>(g0,g1,g2,g3,g4,g5,g6,g7,g8,g9); STOREG(2);
    }
    __syncthreads();

    // ---- Phase B: fwd 9-pt (3x3) -> weight -> inv 9-pt, in registers
    {
        const int HS = Wn*KD*CT;
        const int WS = Wn*KD*DIMC;
        for (int it = tid; it < Wn*KD*CT; it += NTHREADS) {
            int c  = it % CT;
            int wk = it / CT;
            int w = wk / KD, k = wk % KD;
            int base = (w*KD + k)*CT + c;
            const float2* cwp = cw2 + (long)((w*KD) + k)*DIMC + c0 + c;
            float2 a0=z[base+0*HS], a1=z[base+1*HS], a2=z[base+2*HS],
                   a3=z[base+3*HS], a4=z[base+4*HS], a5=z[base+5*HS],
                   a6=z[base+6*HS], a7=z[base+7*HS], a8=z[base+8*HS];
            float2 A00,A10,A20, A01,A11,A21, A02,A12,A22;
            dft3<+1>(a0,a3,a6, A00,A10,A20);
            dft3<+1>(a1,a4,a7, A01,A11,A21);
            dft3<+1>(a2,a5,a8, A02,A12,A22);
            A11 = cmul(A11, C91, -S91);
            A12 = cmul(A12, C92, -S92);
            A21 = cmul(A21, C92, -S92);
            A22 = cmul(A22, C94, -S94);
            float2 X0,X3,X6, X1,X4,X7, X2,X5,X8;
            dft3<+1>(A00,A01,A02, X0,X3,X6);
            dft3<+1>(A10,A11,A12, X1,X4,X7);
            dft3<+1>(A20,A21,A22, X2,X5,X8);
            X0 = wmul(X0, cwp[0*WS]); X1 = wmul(X1, cwp[1*WS]); X2 = wmul(X2, cwp[2*WS]);
            X3 = wmul(X3, cwp[3*WS]); X4 = wmul(X4, cwp[4*WS]); X5 = wmul(X5, cwp[5*WS]);
            X6 = wmul(X6, cwp[6*WS]); X7 = wmul(X7, cwp[7*WS]); X8 = wmul(X8, cwp[8*WS]);
            float2 P00,P10,P20, P01,P11,P21, P02,P12,P22;
            dft3<-1>(X0,X3,X6, P00,P10,P20);
            dft3<-1>(X1,X4,X7, P01,P11,P21);
            dft3<-1>(X2,X5,X8, P02,P12,P22);
            P11 = cmul(P11, C91, S91);
            P12 = cmul(P12, C92, S92);
            P21 = cmul(P21, C92, S92);
            P22 = cmul(P22, C94, S94);
            float2 y0,y3,y6, y1,y4,y7, y2,y5,y8;
            dft3<-1>(P00,P01,P02, y0,y3,y6);
            dft3<-1>(P10,P11,P12, y1,y4,y7);
            dft3<-1>(P20,P21,P22, y2,y5,y8);
            z[base+0*HS]=y0; z[base+1*HS]=y1; z[base+2*HS]=y2;
            z[base+3*HS]=y3; z[base+4*HS]=y4; z[base+5*HS]=y5;
            z[base+6*HS]=y6; z[base+7*HS]=y7; z[base+8*HS]=y8;
        }
    }
    __syncthreads();

    // ---- Phase C: thread owns (h, c) pencil. k0 first with Re-only ifft10
    //      (10 floats), then k1 and k2 full; combine via irfft5 and store.
    for (int it = tid; it < Hn*CT; it += NTHREADS) {
        int c = it % CT, h = it / CT;
        int zb = (h*Wn*KD)*CT + c;
        float s0,s1,s2,s3,s4,s5,s6,s7,s8,s9;
        float2 u0,u1,u2,u3,u4,u5,u6,u7,u8,u9;
        float2 q0,q1,q2,q3,q4,q5,q6,q7,q8,q9;
        LOADQ(0);
        ifft10_re(q0,q1,q2,q3,q4,q5,q6,q7,q8,q9,
                  s0,s1,s2,s3,s4,s5,s6,s7,s8,s9);
        LOADU(1);
        fft10s<-1>(u0,u1,u2,u3,u4,u5,u6,u7,u8,u9);
        LOADQ(2);
        fft10s<-1>(q0,q1,q2,q3,q4,q5,q6,q7,q8,q9);
        float* po = out + xbase + (long)h * (Wn*Dn*DIMC) + c;
        OUTW(0); OUTW(1); OUTW(2); OUTW(3); OUTW(4);
        OUTW(5); OUTW(6); OUTW(7); OUTW(8); OUTW(9);
    }
}

extern "C" void kernel_launch(void* const* d_in, const int* in_sizes, int n_in,
                              void* d_out, int out_size) {
    const float*  x   = (const float*)d_in[0];    // (B, 450, 1000) f32
    const float2* cw2 = (const float2*)d_in[1];   // (9, 10, 3, 1000, 2) f32
    float* out = (float*)d_out;                   // (B, 450, 1000) f32
    const int B = in_sizes[0] / (NSP * DIMC);
    dim3 grid(B, DIMC / CT);
    gf_kernel<<<grid, NTHREADS>>>(x, cw2, out);
}